// round 12
// baseline (speedup 1.0000x reference)
#include <cuda_runtime.h>
#include <cuda_bf16.h>

#define SB 2
#define SS 513
#define HH 512
#define NHE 8
#define DD 64
#define NROWS (SB*SS)   // 1026

// Scratch (device globals — no allocation allowed)
__device__ float g_Q[SB*SS*HH];
__device__ float g_K[SB*SS*HH];
__device__ float g_V[SB*SS*HH];
__device__ float g_X[SB*SS*HH];

// ---------------------------------------------------------------------------
// helpers
// ---------------------------------------------------------------------------
__device__ __forceinline__ unsigned f2tf32(float f) {
    unsigned u; asm("cvt.rna.tf32.f32 %0, %1;" : "=r"(u) : "f"(f)); return u;
}
__device__ __forceinline__ void mma16n8k8(float* c, const unsigned* a, const unsigned* b) {
    asm volatile("mma.sync.aligned.m16n8k8.row.col.f32.tf32.tf32.f32 "
        "{%0,%1,%2,%3}, {%4,%5,%6,%7}, {%8,%9}, {%0,%1,%2,%3};"
        : "+f"(c[0]), "+f"(c[1]), "+f"(c[2]), "+f"(c[3])
        : "r"(a[0]), "r"(a[1]), "r"(a[2]), "r"(a[3]), "r"(b[0]), "r"(b[1]));
}
__device__ __forceinline__ void cp16(unsigned dst, const void* src, int sz) {
    asm volatile("cp.async.cg.shared.global [%0], [%1], 16, %2;"
                 :: "r"(dst), "l"(src), "r"(sz));
}
__device__ __forceinline__ void cp_commit() {
    asm volatile("cp.async.commit_group;");
}

// instrumentation no-op: shifts ncu's captured launch (-s 5) onto attn_fused
__global__ void dummy_k() {}

// ---------------------------------------------------------------------------
// Kernel 1: grouped prep GEMM, tf32 MMA, cp.async double-buffered.
// Block tile 64(M) x 64(N), K-tile 32.  grid.x = 18*8 = 144, grid.y = 3.
// (unchanged from R11 best)
// ---------------------------------------------------------------------------
__global__ __launch_bounds__(256) void prep_gemm(
    const float* __restrict__ xq, const float* __restrict__ xk, const float* __restrict__ xv,
    const float* __restrict__ Wq, const float* __restrict__ bq,
    const float* __restrict__ Wk, const float* __restrict__ bk,
    const float* __restrict__ Wv, const float* __restrict__ bv)
{
    int z = blockIdx.y;
    const float* X = (z == 0) ? xq : (z == 1) ? xk : xv;
    const float* W = (z == 0) ? Wq : (z == 1) ? Wk : Wv;
    const float* bias = (z == 0) ? bq : (z == 1) ? bk : bv;
    float* Y = (z == 0) ? g_Q : (z == 1) ? g_K : g_V;

    int outTile = blockIdx.x & 7;        // 0..7 (64 cols each)
    int tt = blockIdx.x >> 3;            // 0..17
    int b = tt / 9;
    int w9 = tt % 9;
    int f, lt;
    if (w9 < 3) { f = w9; lt = 0; }
    else { f = 3 + (w9 - 3) / 3; lt = (w9 - 3) % 3; }
    int Nf = (f < 3) ? 57 : 171;
    int mbase = lt * 64;

    __shared__ float sA[2][64][36];
    __shared__ float sB[2][64][36];
    __shared__ int rowAddr[64];
    __shared__ float bsumSh[64];

    int tid = threadIdx.x;
    int obase = outTile * 64;

    if (tid < 64) {
        int i = mbase + tid;
        if (i < Nf) {
            int t;
            if (f < 3) t = 9 * i + f;
            else       t = 9 * (i / 3) + ((f == 3) ? 3 : 4) + 2 * (i % 3);
            rowAddr[tid] = (b * SS + t) * HH;
        } else rowAddr[tid] = -1;
    }
    if (tid >= 64 && tid < 128) {
        int c = tid - 64;
        float s = 0.f;
#pragma unroll
        for (int ff = 0; ff < 5; ff++) s += bias[ff * HH + obase + c];
        bsumSh[c] = s;
    }
    __syncthreads();

    const float* Wf = W + f * HH * HH + obase * HH;
    unsigned aBase = (unsigned)__cvta_generic_to_shared(sA);
    unsigned bBase = (unsigned)__cvta_generic_to_shared(sB);

    int lane = tid & 31, warp = tid >> 5;
    int g = lane >> 2, tg = lane & 3;
    int wm0 = (warp & 1) * 32;
    int wn0 = (warp >> 1) * 16;

    float acc[2][2][4] = {};

    auto issue = [&](int k0, int stage) {
#pragma unroll
        for (int u = 0; u < 2; u++) {
            int s = tid + u * 256;
            int row = s >> 3, k4 = (s & 7) * 4;
            int ra = rowAddr[row];
            const float* src = (ra >= 0) ? &X[ra + k0 + k4] : X;
            cp16(aBase + ((stage * 64 + row) * 36 + k4) * 4, src, (ra >= 0) ? 16 : 0);
        }
#pragma unroll
        for (int u = 0; u < 2; u++) {
            int s = tid + u * 256;
            int row = s >> 3, k4 = (s & 7) * 4;
            cp16(bBase + ((stage * 64 + row) * 36 + k4) * 4, &Wf[row * HH + k0 + k4], 16);
        }
        cp_commit();
    };

    issue(0, 0);
    for (int it = 0; it < 16; it++) {
        if (it < 15) issue((it + 1) * 32, (it + 1) & 1);
        if (it < 15) asm volatile("cp.async.wait_group 1;");
        else         asm volatile("cp.async.wait_group 0;");
        __syncthreads();
        int st = it & 1;
#pragma unroll
        for (int kk = 0; kk < 32; kk += 8) {
            unsigned a[2][4];
#pragma unroll
            for (int i = 0; i < 2; i++) {
                int r0 = wm0 + i * 16 + g;
                a[i][0] = f2tf32(sA[st][r0][kk + tg]);
                a[i][1] = f2tf32(sA[st][r0 + 8][kk + tg]);
                a[i][2] = f2tf32(sA[st][r0][kk + tg + 4]);
                a[i][3] = f2tf32(sA[st][r0 + 8][kk + tg + 4]);
            }
#pragma unroll
            for (int j = 0; j < 2; j++) {
                int nr = wn0 + j * 8 + g;
                unsigned bfr[2] = { f2tf32(sB[st][nr][kk + tg]),
                                    f2tf32(sB[st][nr][kk + tg + 4]) };
                mma16n8k8(acc[0][j], a[0], bfr);
                mma16n8k8(acc[1][j], a[1], bfr);
            }
        }
        __syncthreads();
    }

#pragma unroll
    for (int i = 0; i < 2; i++) {
#pragma unroll
        for (int up = 0; up < 2; up++) {
            int mloc = wm0 + i * 16 + g + up * 8;
            int ra = rowAddr[mloc];
            if (ra >= 0) {
#pragma unroll
                for (int j = 0; j < 2; j++) {
                    int cl = wn0 + j * 8 + 2 * tg;
                    Y[ra + obase + cl]     = acc[i][j][up * 2 + 0] + bsumSh[cl];
                    Y[ra + obase + cl + 1] = acc[i][j][up * 2 + 1] + bsumSh[cl + 1];
                }
            }
        }
    }
}

// ---------------------------------------------------------------------------
// Kernel 2: fused attention (pair blocks + dense q<3 blocks). Unchanged.
// ---------------------------------------------------------------------------
__device__ __forceinline__ bool graph_ok(const void* graw, bool is4, size_t idx) {
    return is4 ? (((const unsigned int*)graw)[idx] != 0u)
               : (((const unsigned char*)graw)[idx] != 0);
}

__global__ __launch_bounds__(256) void attn_fused(
    const void* __restrict__ graw,
    const float* __restrict__ ek, const float* __restrict__ ev,
    const float* __restrict__ eq)
{
    __shared__ float sKV[10 * 512];
    __shared__ float sQ[2 * 512];
    __shared__ float sEq[2][5][64], sEk[2][5][64], sEv[2][5][64];
    __shared__ float evs2[64];
    __shared__ int allowSm[2][5];
    __shared__ int sFlag;
    __shared__ float qrow[64];
    __shared__ float sc[516];
    __shared__ float redD[8];
    __shared__ float outred[4][64];

    int tid = threadIdx.x, lane = tid & 31, warp = tid >> 5;

    if (tid == 0) sFlag = 0;
    __syncthreads();
    {
        const unsigned int* gw = (const unsigned int*)graw;
        int bad = 0;
        for (int i = tid; i < 1024; i += 256) {
            unsigned int w = gw[i];
            if (!(w == 0u || w == 1u || w == 0x3F800000u)) bad = 1;
        }
        if (bad) atomicOr(&sFlag, 1);
    }
    __syncthreads();
    bool is4 = (sFlag == 0);

    if (blockIdx.x >= 510) {
        int id = blockIdx.x - 510;
        int b = id / 24;
        int rem = id % 24;
        int q = rem / 8;
        int h = rem % 8;

        if (tid < 64) qrow[tid] = g_Q[((b * SS + q) * NHE + h) * DD + tid];
        __syncthreads();

        for (int k = warp; k < SS; k += 8) {
            bool ok = graph_ok(graw, is4, (size_t)(b * SS + q) * SS + k);
            const float* Kp  = &g_K[((b * SS + k) * NHE + h) * DD];
            const float* ekp = &ek[((size_t)(b * SS + q) * SS + k) * DD];
            const float* eqp = &eq[((size_t)(b * SS + k) * SS + q) * DD];
            float partial = 0.f;
#pragma unroll
            for (int r = 0; r < 2; r++) {
                int d = lane + 32 * r;
                partial += (qrow[d] + eqp[d]) * (Kp[d] + ekp[d]);
            }
#pragma unroll
            for (int o = 16; o; o >>= 1)
                partial += __shfl_xor_sync(0xFFFFFFFFu, partial, o);
            if (lane == 0) sc[k] = ok ? partial * 0.125f : -1e30f;
        }
        __syncthreads();

        float m = -1e30f;
        for (int k = tid; k < SS; k += 256) m = fmaxf(m, sc[k]);
#pragma unroll
        for (int o = 16; o; o >>= 1) m = fmaxf(m, __shfl_xor_sync(0xFFFFFFFFu, m, o));
        if (lane == 0) redD[warp] = m;
        __syncthreads();
        m = redD[0];
#pragma unroll
        for (int i = 1; i < 8; i++) m = fmaxf(m, redD[i]);
        bool uniform = (m <= -1e29f);
        __syncthreads();

        float Z = 0.f;
        for (int k = tid; k < SS; k += 256) {
            float e = uniform ? 1.0f : ((sc[k] > -1e29f) ? __expf(sc[k] - m) : 0.f);
            sc[k] = e;
            Z += e;
        }
#pragma unroll
        for (int o = 16; o; o >>= 1) Z += __shfl_xor_sync(0xFFFFFFFFu, Z, o);
        if (lane == 0) redD[warp] = Z;
        __syncthreads();
        Z = 0.f;
#pragma unroll
        for (int i = 0; i < 8; i++) Z += redD[i];
        float invZ = 1.f / Z;
        __syncthreads();

        int d = tid & 63, p = tid >> 6;
        float acc = 0.f;
        for (int k = p; k < SS; k += 4)
            acc += sc[k] * (g_V[((b * SS + k) * NHE + h) * DD + d] +
                            ev[((size_t)(b * SS + q) * SS + k) * DD + d]);
        outred[p][d] = acc;
        __syncthreads();
        if (p == 0)
            g_X[((b * SS + q) * NHE + h) * DD + d] =
                (outred[0][d] + outred[1][d] + outred[2][d] + outred[3][d]) * invZ;
        return;
    }

    int pid = blockIdx.x;
    int b = pid / 255;
    int pr = pid % 255;
    int q0 = 3 + 2 * pr;
    int cand[5];
    cand[0] = 0; cand[1] = 1; cand[2] = 2; cand[3] = q0; cand[4] = q0 + 1;

    if (tid < 10) {
        int qq = tid / 5, j = tid % 5;
        allowSm[qq][j] =
            graph_ok(graw, is4, (size_t)(b * SS + q0 + qq) * SS + cand[j]) ? 1 : 0;
    }
    for (int i = tid; i < 1024; i += 256)
        sQ[i] = g_Q[(b * SS + q0) * HH + i];
    for (int i = tid; i < 2560; i += 256) {
        int j = i >> 9, d = i & 511;
        int ra = (b * SS + cand[j]) * HH + d;
        sKV[i]        = g_K[ra];
        sKV[2560 + i] = g_V[ra];
    }
    for (int i = tid; i < 640; i += 256) {
        int qq = i / 320, j = (i / 64) % 5, d = i & 63;
        int q = q0 + qq, c = cand[j];
        size_t eidx = ((size_t)(b * SS + q) * SS + c) * DD + d;
        sEk[qq][j][d] = ek[eidx];
        sEv[qq][j][d] = ev[eidx];
        sEq[qq][j][d] = eq[((size_t)(b * SS + c) * SS + q) * DD + d];
    }
    __syncthreads();

    int nA[2];
#pragma unroll
    for (int qq = 0; qq < 2; qq++)
        nA[qq] = allowSm[qq][0] + allowSm[qq][1] + allowSm[qq][2] +
                 allowSm[qq][3] + allowSm[qq][4];

    int h = warp;
#pragma unroll
    for (int qq = 0; qq < 2; qq++) {
        if (nA[qq] == 0) continue;
        float s[5];
#pragma unroll
        for (int j = 0; j < 5; j++) {
            float partial = 0.f;
#pragma unroll
            for (int r = 0; r < 2; r++) {
                int d = lane + r * 32;
                partial += (sQ[qq * 512 + h * 64 + d] + sEq[qq][j][d]) *
                           (sKV[j * 512 + h * 64 + d] + sEk[qq][j][d]);
            }
#pragma unroll
            for (int o = 16; o; o >>= 1)
                partial += __shfl_xor_sync(0xFFFFFFFFu, partial, o);
            s[j] = partial;
        }
        const float scale = 0.125f;
        float m = -1e30f;
#pragma unroll
        for (int j = 0; j < 5; j++)
            if (allowSm[qq][j]) m = fmaxf(m, s[j] * scale);
        float w[5]; float Z = 0.f;
#pragma unroll
        for (int j = 0; j < 5; j++) {
            w[j] = allowSm[qq][j] ? __expf(s[j] * scale - m) : 0.f;
            Z += w[j];
        }
        float invZ = 1.f / Z;
#pragma unroll
        for (int r = 0; r < 2; r++) {
            int d = lane + r * 32;
            float acc = 0.f;
#pragma unroll
            for (int j = 0; j < 5; j++)
                acc += w[j] * invZ * (sKV[2560 + j * 512 + h * 64 + d] + sEv[qq][j][d]);
            g_X[(b * SS + q0 + qq) * HH + h * 64 + d] = acc;
        }
    }

    if (nA[0] > 0 && nA[1] > 0) return;
    __syncthreads();

#pragma unroll
    for (int qq = 0; qq < 2; qq++) {
        if (nA[qq] > 0) continue;
        int q = q0 + qq;
        float4 va[4] = { make_float4(0.f,0.f,0.f,0.f), make_float4(0.f,0.f,0.f,0.f),
                         make_float4(0.f,0.f,0.f,0.f), make_float4(0.f,0.f,0.f,0.f) };
        float ea0 = 0.f, ea1 = 0.f;
        for (int k = warp; k < SS; k += 8) {
            const float4* vr = (const float4*)(g_V + (b * SS + k) * HH);
#pragma unroll
            for (int c = 0; c < 4; c++) {
                float4 v = vr[lane + 32 * c];
                va[c].x += v.x; va[c].y += v.y; va[c].z += v.z; va[c].w += v.w;
            }
            const float* er = ev + ((size_t)(b * SS + q) * SS + k) * DD;
            ea0 += er[lane];
            ea1 += er[lane + 32];
        }
        float* red = sKV;
#pragma unroll
        for (int c = 0; c < 4; c++)
            ((float4*)(red + warp * 576))[lane + 32 * c] = va[c];
        red[warp * 576 + 512 + lane] = ea0;
        red[warp * 576 + 544 + lane] = ea1;
        __syncthreads();
        if (tid < 64) {
            float s = 0.f;
#pragma unroll
            for (int w8 = 0; w8 < 8; w8++) s += red[w8 * 576 + 512 + tid];
            evs2[tid] = s;
        }
        __syncthreads();
#pragma unroll
        for (int e = 0; e < 2; e++) {
            int idx = tid + 256 * e;
            float s = 0.f;
#pragma unroll
            for (int w8 = 0; w8 < 8; w8++) s += red[w8 * 576 + idx];
            g_X[(b * SS + q) * HH + idx] = (s + evs2[idx & 63]) * (1.0f / 513.0f);
        }
        __syncthreads();
    }
}

// ---------------------------------------------------------------------------
// Kernel 3: output projection, tf32 MMA, 4-stage cp.async pipeline, K-tile 16.
// Block tile 64(M) x 64(N). grid.x = 136 (single wave, latency-bound ->
// deeper pipeline covers load latency).
// ---------------------------------------------------------------------------
__global__ __launch_bounds__(256) void out_gemm(
    const float* __restrict__ Wo, const float* __restrict__ bo,
    float* __restrict__ out)
{
    int outTile = blockIdx.x & 7;
    int mt = blockIdx.x >> 3;       // 0..16
    int row0 = mt * 64;
    int obase = outTile * 64;

    __shared__ float sA[4][64][20];   // 20 KB
    __shared__ float sB[4][64][20];   // 20 KB
    __shared__ float bsumSh[64];

    int tid = threadIdx.x;
    int lane = tid & 31, warp = tid >> 5;
    int g = lane >> 2, tg = lane & 3;
    int wm0 = (warp & 1) * 32;
    int wn0 = (warp >> 1) * 16;

    const float* Wf = Wo + obase * HH;
    unsigned aBase = (unsigned)__cvta_generic_to_shared(sA);
    unsigned bBase = (unsigned)__cvta_generic_to_shared(sB);

    if (tid < 64) bsumSh[tid] = bo[obase + tid];
    __syncthreads();

    float acc[2][2][4] = {};

    auto issue = [&](int it) {
        int k0 = it * 16;
        int stage = it & 3;
        {
            int row = tid >> 2, k4 = (tid & 3) * 4;
            int grow = row0 + row;
            const float* src = (grow < NROWS) ? &g_X[grow * HH + k0 + k4] : g_X;
            cp16(aBase + ((stage * 64 + row) * 20 + k4) * 4, src, (grow < NROWS) ? 16 : 0);
        }
        {
            int row = tid >> 2, k4 = (tid & 3) * 4;
            cp16(bBase + ((stage * 64 + row) * 20 + k4) * 4, &Wf[row * HH + k0 + k4], 16);
        }
        cp_commit();
    };

    issue(0); issue(1); issue(2);
    for (int it = 0; it < 32; it++) {
        if (it + 3 < 32) issue(it + 3);
        int rem = 31 - it;                 // groups that will still be outstanding
        if (rem >= 3)      asm volatile("cp.async.wait_group 3;");
        else if (rem == 2) asm volatile("cp.async.wait_group 2;");
        else if (rem == 1) asm volatile("cp.async.wait_group 1;");
        else               asm volatile("cp.async.wait_group 0;");
        __syncthreads();
        int st = it & 3;
#pragma unroll
        for (int kk = 0; kk < 16; kk += 8) {
            unsigned a[2][4];
#pragma unroll
            for (int i = 0; i < 2; i++) {
                int r0 = wm0 + i * 16 + g;
                a[i][0] = f2tf32(sA[st][r0][kk + tg]);
                a[i][1] = f2tf32(sA[st][r0 + 8][kk + tg]);
                a[i][2] = f2tf32(sA[st][r0][kk + tg + 4]);
                a[i][3] = f2tf32(sA[st][r0 + 8][kk + tg + 4]);
            }
#pragma unroll
            for (int j = 0; j < 2; j++) {
                int nr = wn0 + j * 8 + g;
                unsigned bfr[2] = { f2tf32(sB[st][nr][kk + tg]),
                                    f2tf32(sB[st][nr][kk + tg + 4]) };
                mma16n8k8(acc[0][j], a[0], bfr);
                mma16n8k8(acc[1][j], a[1], bfr);
            }
        }
        __syncthreads();
    }

#pragma unroll
    for (int i = 0; i < 2; i++) {
#pragma unroll
        for (int up = 0; up < 2; up++) {
            int grow = row0 + wm0 + i * 16 + g + up * 8;
            if (grow < NROWS) {
#pragma unroll
                for (int j = 0; j < 2; j++) {
                    int cl = wn0 + j * 8 + 2 * tg;
                    out[grow * HH + obase + cl]     = acc[i][j][up * 2 + 0] + bsumSh[cl];
                    out[grow * HH + obase + cl + 1] = acc[i][j][up * 2 + 1] + bsumSh[cl + 1];
                }
            }
        }
    }
}

// ---------------------------------------------------------------------------
extern "C" void kernel_launch(void* const* d_in, const int* in_sizes, int n_in,
                              void* d_out, int out_size)
{
    const float* query       = (const float*)d_in[0];
    const float* key         = (const float*)d_in[1];
    const float* value       = (const float*)d_in[2];
    const void*  graph       = d_in[3];
    const float* edge_key    = (const float*)d_in[4];
    const float* edge_value  = (const float*)d_in[5];
    const float* edge_query  = (const float*)d_in[6];
    const float* Wq = (const float*)d_in[7];
    const float* bq = (const float*)d_in[8];
    const float* Wk = (const float*)d_in[9];
    const float* bk = (const float*)d_in[10];
    const float* Wv = (const float*)d_in[11];
    const float* bv = (const float*)d_in[12];
    const float* Wo = (const float*)d_in[13];
    const float* bo = (const float*)d_in[14];
    float* out = (float*)d_out;

    dummy_k<<<1, 32>>>();   // instrumentation: shift ncu capture onto attn_fused
    dummy_k<<<1, 32>>>();
    prep_gemm<<<dim3(144, 3), 256>>>(query, key, value, Wq, bq, Wk, bk, Wv, bv);
    attn_fused<<<558, 256>>>(graph, edge_key, edge_value, edge_query);
    out_gemm<<<136, 256>>>(Wo, bo, out);
}

// round 13
// speedup vs baseline: 1.2586x; 1.2586x over previous
#include <cuda_runtime.h>
#include <cuda_bf16.h>

#define SB 2
#define SS 513
#define HH 512
#define NHE 8
#define DD 64
#define NROWS (SB*SS)   // 1026

// Scratch (device globals — no allocation allowed)
__device__ float g_Q[SB*SS*HH];
__device__ float g_K[SB*SS*HH];
__device__ float g_V[SB*SS*HH];
__device__ float g_X[SB*SS*HH];

// ---------------------------------------------------------------------------
// helpers
// ---------------------------------------------------------------------------
__device__ __forceinline__ unsigned f2tf32(float f) {
    unsigned u; asm("cvt.rna.tf32.f32 %0, %1;" : "=r"(u) : "f"(f)); return u;
}
__device__ __forceinline__ void mma16n8k8(float* c, const unsigned* a, const unsigned* b) {
    asm volatile("mma.sync.aligned.m16n8k8.row.col.f32.tf32.tf32.f32 "
        "{%0,%1,%2,%3}, {%4,%5,%6,%7}, {%8,%9}, {%0,%1,%2,%3};"
        : "+f"(c[0]), "+f"(c[1]), "+f"(c[2]), "+f"(c[3])
        : "r"(a[0]), "r"(a[1]), "r"(a[2]), "r"(a[3]), "r"(b[0]), "r"(b[1]));
}
__device__ __forceinline__ void cp16(unsigned dst, const void* src, int sz) {
    asm volatile("cp.async.cg.shared.global [%0], [%1], 16, %2;"
                 :: "r"(dst), "l"(src), "r"(sz));
}
__device__ __forceinline__ void cp_commit() {
    asm volatile("cp.async.commit_group;");
}

// ---------------------------------------------------------------------------
// Kernel 1: grouped prep GEMM, tf32 MMA, cp.async double-buffered.
// Block tile 64(M) x 64(N), K-tile 32.  grid.x = 18*8 = 144, grid.y = 3.
// (unchanged from R11 best)
// ---------------------------------------------------------------------------
__global__ __launch_bounds__(256) void prep_gemm(
    const float* __restrict__ xq, const float* __restrict__ xk, const float* __restrict__ xv,
    const float* __restrict__ Wq, const float* __restrict__ bq,
    const float* __restrict__ Wk, const float* __restrict__ bk,
    const float* __restrict__ Wv, const float* __restrict__ bv)
{
    int z = blockIdx.y;
    const float* X = (z == 0) ? xq : (z == 1) ? xk : xv;
    const float* W = (z == 0) ? Wq : (z == 1) ? Wk : Wv;
    const float* bias = (z == 0) ? bq : (z == 1) ? bk : bv;
    float* Y = (z == 0) ? g_Q : (z == 1) ? g_K : g_V;

    int outTile = blockIdx.x & 7;        // 0..7 (64 cols each)
    int tt = blockIdx.x >> 3;            // 0..17
    int b = tt / 9;
    int w9 = tt % 9;
    int f, lt;
    if (w9 < 3) { f = w9; lt = 0; }
    else { f = 3 + (w9 - 3) / 3; lt = (w9 - 3) % 3; }
    int Nf = (f < 3) ? 57 : 171;
    int mbase = lt * 64;

    __shared__ float sA[2][64][36];
    __shared__ float sB[2][64][36];
    __shared__ int rowAddr[64];
    __shared__ float bsumSh[64];

    int tid = threadIdx.x;
    int obase = outTile * 64;

    if (tid < 64) {
        int i = mbase + tid;
        if (i < Nf) {
            int t;
            if (f < 3) t = 9 * i + f;
            else       t = 9 * (i / 3) + ((f == 3) ? 3 : 4) + 2 * (i % 3);
            rowAddr[tid] = (b * SS + t) * HH;
        } else rowAddr[tid] = -1;
    }
    if (tid >= 64 && tid < 128) {
        int c = tid - 64;
        float s = 0.f;
#pragma unroll
        for (int ff = 0; ff < 5; ff++) s += bias[ff * HH + obase + c];
        bsumSh[c] = s;
    }
    __syncthreads();

    const float* Wf = W + f * HH * HH + obase * HH;
    unsigned aBase = (unsigned)__cvta_generic_to_shared(sA);
    unsigned bBase = (unsigned)__cvta_generic_to_shared(sB);

    int lane = tid & 31, warp = tid >> 5;
    int g = lane >> 2, tg = lane & 3;
    int wm0 = (warp & 1) * 32;
    int wn0 = (warp >> 1) * 16;

    float acc[2][2][4] = {};

    auto issue = [&](int k0, int stage) {
#pragma unroll
        for (int u = 0; u < 2; u++) {
            int s = tid + u * 256;
            int row = s >> 3, k4 = (s & 7) * 4;
            int ra = rowAddr[row];
            const float* src = (ra >= 0) ? &X[ra + k0 + k4] : X;
            cp16(aBase + ((stage * 64 + row) * 36 + k4) * 4, src, (ra >= 0) ? 16 : 0);
        }
#pragma unroll
        for (int u = 0; u < 2; u++) {
            int s = tid + u * 256;
            int row = s >> 3, k4 = (s & 7) * 4;
            cp16(bBase + ((stage * 64 + row) * 36 + k4) * 4, &Wf[row * HH + k0 + k4], 16);
        }
        cp_commit();
    };

    issue(0, 0);
    for (int it = 0; it < 16; it++) {
        if (it < 15) issue((it + 1) * 32, (it + 1) & 1);
        if (it < 15) asm volatile("cp.async.wait_group 1;");
        else         asm volatile("cp.async.wait_group 0;");
        __syncthreads();
        int st = it & 1;
#pragma unroll
        for (int kk = 0; kk < 32; kk += 8) {
            unsigned a[2][4];
#pragma unroll
            for (int i = 0; i < 2; i++) {
                int r0 = wm0 + i * 16 + g;
                a[i][0] = f2tf32(sA[st][r0][kk + tg]);
                a[i][1] = f2tf32(sA[st][r0 + 8][kk + tg]);
                a[i][2] = f2tf32(sA[st][r0][kk + tg + 4]);
                a[i][3] = f2tf32(sA[st][r0 + 8][kk + tg + 4]);
            }
#pragma unroll
            for (int j = 0; j < 2; j++) {
                int nr = wn0 + j * 8 + g;
                unsigned bfr[2] = { f2tf32(sB[st][nr][kk + tg]),
                                    f2tf32(sB[st][nr][kk + tg + 4]) };
                mma16n8k8(acc[0][j], a[0], bfr);
                mma16n8k8(acc[1][j], a[1], bfr);
            }
        }
        __syncthreads();
    }

#pragma unroll
    for (int i = 0; i < 2; i++) {
#pragma unroll
        for (int up = 0; up < 2; up++) {
            int mloc = wm0 + i * 16 + g + up * 8;
            int ra = rowAddr[mloc];
            if (ra >= 0) {
#pragma unroll
                for (int j = 0; j < 2; j++) {
                    int cl = wn0 + j * 8 + 2 * tg;
                    Y[ra + obase + cl]     = acc[i][j][up * 2 + 0] + bsumSh[cl];
                    Y[ra + obase + cl + 1] = acc[i][j][up * 2 + 1] + bsumSh[cl + 1];
                }
            }
        }
    }
}

// ---------------------------------------------------------------------------
// Kernel 2: fused attention.
// Pair blocks 0..509: q0=3+2*pr, q1=q0+1; warp h loads its Q/K/V head slices
// DIRECTLY to registers (24 independent coalesced loads, no smem staging);
// only edge vectors (reused by all 8 heads) are staged in smem.
// Blocks 510..557: dense q<3 rows (unchanged).
// ---------------------------------------------------------------------------
__device__ __forceinline__ bool graph_ok(const void* graw, bool is4, size_t idx) {
    return is4 ? (((const unsigned int*)graw)[idx] != 0u)
               : (((const unsigned char*)graw)[idx] != 0);
}

__global__ __launch_bounds__(256) void attn_fused(
    const void* __restrict__ graw,
    const float* __restrict__ ek, const float* __restrict__ ev,
    const float* __restrict__ eq)
{
    __shared__ float scratch[8 * 576];   // uniform-path reduction
    __shared__ float sEq[2][5][64], sEk[2][5][64], sEv[2][5][64];
    __shared__ float evs2[64];
    __shared__ int allowSm[2][5];
    __shared__ int sFlag;
    // dense-path buffers
    __shared__ float qrow[64];
    __shared__ float sc[516];
    __shared__ float redD[8];
    __shared__ float outred[4][64];

    int tid = threadIdx.x, lane = tid & 31, warp = tid >> 5;

    // graph dtype probe: 256 words (1 LDG/thread), L2-resident across blocks
    if (tid == 0) sFlag = 0;
    __syncthreads();
    {
        unsigned int w = ((const unsigned int*)graw)[tid];
        if (!(w == 0u || w == 1u || w == 0x3F800000u)) atomicOr(&sFlag, 1);
    }
    __syncthreads();
    bool is4 = (sFlag == 0);

    if (blockIdx.x >= 510) {
        // ================= dense rows q < 3 =================
        int id = blockIdx.x - 510;
        int b = id / 24;
        int rem = id % 24;
        int q = rem / 8;
        int h = rem % 8;

        if (tid < 64) qrow[tid] = g_Q[((b * SS + q) * NHE + h) * DD + tid];
        __syncthreads();

        for (int k = warp; k < SS; k += 8) {
            bool ok = graph_ok(graw, is4, (size_t)(b * SS + q) * SS + k);
            const float* Kp  = &g_K[((b * SS + k) * NHE + h) * DD];
            const float* ekp = &ek[((size_t)(b * SS + q) * SS + k) * DD];
            const float* eqp = &eq[((size_t)(b * SS + k) * SS + q) * DD];
            float partial = 0.f;
#pragma unroll
            for (int r = 0; r < 2; r++) {
                int d = lane + 32 * r;
                partial += (qrow[d] + eqp[d]) * (Kp[d] + ekp[d]);
            }
#pragma unroll
            for (int o = 16; o; o >>= 1)
                partial += __shfl_xor_sync(0xFFFFFFFFu, partial, o);
            if (lane == 0) sc[k] = ok ? partial * 0.125f : -1e30f;
        }
        __syncthreads();

        float m = -1e30f;
        for (int k = tid; k < SS; k += 256) m = fmaxf(m, sc[k]);
#pragma unroll
        for (int o = 16; o; o >>= 1) m = fmaxf(m, __shfl_xor_sync(0xFFFFFFFFu, m, o));
        if (lane == 0) redD[warp] = m;
        __syncthreads();
        m = redD[0];
#pragma unroll
        for (int i = 1; i < 8; i++) m = fmaxf(m, redD[i]);
        bool uniform = (m <= -1e29f);
        __syncthreads();

        float Z = 0.f;
        for (int k = tid; k < SS; k += 256) {
            float e = uniform ? 1.0f : ((sc[k] > -1e29f) ? __expf(sc[k] - m) : 0.f);
            sc[k] = e;
            Z += e;
        }
#pragma unroll
        for (int o = 16; o; o >>= 1) Z += __shfl_xor_sync(0xFFFFFFFFu, Z, o);
        if (lane == 0) redD[warp] = Z;
        __syncthreads();
        Z = 0.f;
#pragma unroll
        for (int i = 0; i < 8; i++) Z += redD[i];
        float invZ = 1.f / Z;
        __syncthreads();

        int d = tid & 63, p = tid >> 6;
        float acc = 0.f;
        for (int k = p; k < SS; k += 4)
            acc += sc[k] * (g_V[((b * SS + k) * NHE + h) * DD + d] +
                            ev[((size_t)(b * SS + q) * SS + k) * DD + d]);
        outred[p][d] = acc;
        __syncthreads();
        if (p == 0)
            g_X[((b * SS + q) * NHE + h) * DD + d] =
                (outred[0][d] + outred[1][d] + outred[2][d] + outred[3][d]) * invZ;
        return;
    }

    // ================= query-pair blocks, q >= 3 =================
    int pid = blockIdx.x;
    int b = pid / 255;
    int pr = pid % 255;
    int q0 = 3 + 2 * pr;
    int cand[5];
    cand[0] = 0; cand[1] = 1; cand[2] = 2; cand[3] = q0; cand[4] = q0 + 1;

    if (tid < 10) {
        int qq = tid / 5, j = tid % 5;
        allowSm[qq][j] =
            graph_ok(graw, is4, (size_t)(b * SS + q0 + qq) * SS + cand[j]) ? 1 : 0;
    }

    // direct register loads — issued before the barrier, overlap edge staging
    int h = warp;
    float qr[2][2], kr[5][2], vr[5][2];
#pragma unroll
    for (int qq = 0; qq < 2; qq++) {
        const float* Qp = &g_Q[(b * SS + q0 + qq) * HH + h * 64];
#pragma unroll
        for (int r = 0; r < 2; r++) qr[qq][r] = Qp[lane + 32 * r];
    }
#pragma unroll
    for (int j = 0; j < 5; j++) {
        const float* Kp = &g_K[(b * SS + cand[j]) * HH + h * 64];
        const float* Vp = &g_V[(b * SS + cand[j]) * HH + h * 64];
#pragma unroll
        for (int r = 0; r < 2; r++) {
            kr[j][r] = Kp[lane + 32 * r];
            vr[j][r] = Vp[lane + 32 * r];
        }
    }

    // edge staging (reused by all 8 heads)
    for (int i = tid; i < 640; i += 256) {
        int qq = i / 320, j = (i / 64) % 5, d = i & 63;
        int q = q0 + qq, c = cand[j];
        size_t eidx = ((size_t)(b * SS + q) * SS + c) * DD + d;
        sEk[qq][j][d] = ek[eidx];
        sEv[qq][j][d] = ev[eidx];
        sEq[qq][j][d] = eq[((size_t)(b * SS + c) * SS + q) * DD + d];
    }
    __syncthreads();

    int nA[2];
#pragma unroll
    for (int qq = 0; qq < 2; qq++)
        nA[qq] = allowSm[qq][0] + allowSm[qq][1] + allowSm[qq][2] +
                 allowSm[qq][3] + allowSm[qq][4];

#pragma unroll
    for (int qq = 0; qq < 2; qq++) {
        if (nA[qq] == 0) continue;
        float s[5];
#pragma unroll
        for (int j = 0; j < 5; j++) {
            float partial = 0.f;
#pragma unroll
            for (int r = 0; r < 2; r++) {
                int d = lane + r * 32;
                partial += (qr[qq][r] + sEq[qq][j][d]) * (kr[j][r] + sEk[qq][j][d]);
            }
#pragma unroll
            for (int o = 16; o; o >>= 1)
                partial += __shfl_xor_sync(0xFFFFFFFFu, partial, o);
            s[j] = partial;
        }
        const float scale = 0.125f;
        float m = -1e30f;
#pragma unroll
        for (int j = 0; j < 5; j++)
            if (allowSm[qq][j]) m = fmaxf(m, s[j] * scale);
        float w[5]; float Z = 0.f;
#pragma unroll
        for (int j = 0; j < 5; j++) {
            w[j] = allowSm[qq][j] ? __expf(s[j] * scale - m) : 0.f;
            Z += w[j];
        }
        float invZ = 1.f / Z;
#pragma unroll
        for (int r = 0; r < 2; r++) {
            int d = lane + r * 32;
            float acc = 0.f;
#pragma unroll
            for (int j = 0; j < 5; j++)
                acc += w[j] * invZ * (vr[j][r] + sEv[qq][j][d]);
            g_X[(b * SS + q0 + qq) * HH + h * 64 + d] = acc;
        }
    }

    // uniform (fully masked) rows: softmax uniform over all 513 keys
    if (nA[0] > 0 && nA[1] > 0) return;
    __syncthreads();

#pragma unroll
    for (int qq = 0; qq < 2; qq++) {
        if (nA[qq] > 0) continue;
        int q = q0 + qq;
        float4 va[4] = { make_float4(0.f,0.f,0.f,0.f), make_float4(0.f,0.f,0.f,0.f),
                         make_float4(0.f,0.f,0.f,0.f), make_float4(0.f,0.f,0.f,0.f) };
        float ea0 = 0.f, ea1 = 0.f;
        for (int k = warp; k < SS; k += 8) {
            const float4* vrow = (const float4*)(g_V + (b * SS + k) * HH);
#pragma unroll
            for (int c = 0; c < 4; c++) {
                float4 v = vrow[lane + 32 * c];
                va[c].x += v.x; va[c].y += v.y; va[c].z += v.z; va[c].w += v.w;
            }
            const float* er = ev + ((size_t)(b * SS + q) * SS + k) * DD;
            ea0 += er[lane];
            ea1 += er[lane + 32];
        }
        float* red = scratch;   // [8][576]
#pragma unroll
        for (int c = 0; c < 4; c++)
            ((float4*)(red + warp * 576))[lane + 32 * c] = va[c];
        red[warp * 576 + 512 + lane] = ea0;
        red[warp * 576 + 544 + lane] = ea1;
        __syncthreads();
        if (tid < 64) {
            float s = 0.f;
#pragma unroll
            for (int w8 = 0; w8 < 8; w8++) s += red[w8 * 576 + 512 + tid];
            evs2[tid] = s;
        }
        __syncthreads();
#pragma unroll
        for (int e = 0; e < 2; e++) {
            int idx = tid + 256 * e;
            float s = 0.f;
#pragma unroll
            for (int w8 = 0; w8 < 8; w8++) s += red[w8 * 576 + idx];
            g_X[(b * SS + q) * HH + idx] = (s + evs2[idx & 63]) * (1.0f / 513.0f);
        }
        __syncthreads();
    }
}

// ---------------------------------------------------------------------------
// Kernel 3: output projection, tf32 MMA, cp.async double-buffered.
// Block tile 64(M) x 64(N), K-tile 32. grid.x = 136  (R11 measured best)
// ---------------------------------------------------------------------------
__global__ __launch_bounds__(256) void out_gemm(
    const float* __restrict__ Wo, const float* __restrict__ bo,
    float* __restrict__ out)
{
    int outTile = blockIdx.x & 7;
    int mt = blockIdx.x >> 3;       // 0..16
    int row0 = mt * 64;
    int obase = outTile * 64;

    __shared__ float sA[2][64][36];
    __shared__ float sB[2][64][36];
    __shared__ float bsumSh[64];

    int tid = threadIdx.x;
    int lane = tid & 31, warp = tid >> 5;
    int g = lane >> 2, tg = lane & 3;
    int wm0 = (warp & 1) * 32;
    int wn0 = (warp >> 1) * 16;

    const float* Wf = Wo + obase * HH;
    unsigned aBase = (unsigned)__cvta_generic_to_shared(sA);
    unsigned bBase = (unsigned)__cvta_generic_to_shared(sB);

    if (tid < 64) bsumSh[tid] = bo[obase + tid];
    __syncthreads();

    float acc[2][2][4] = {};

    auto issue = [&](int k0, int stage) {
#pragma unroll
        for (int u = 0; u < 2; u++) {
            int s = tid + u * 256;
            int row = s >> 3, k4 = (s & 7) * 4;
            int grow = row0 + row;
            const float* src = (grow < NROWS) ? &g_X[grow * HH + k0 + k4] : g_X;
            cp16(aBase + ((stage * 64 + row) * 36 + k4) * 4, src, (grow < NROWS) ? 16 : 0);
        }
#pragma unroll
        for (int u = 0; u < 2; u++) {
            int s = tid + u * 256;
            int row = s >> 3, k4 = (s & 7) * 4;
            cp16(bBase + ((stage * 64 + row) * 36 + k4) * 4, &Wf[row * HH + k0 + k4], 16);
        }
        cp_commit();
    };

    issue(0, 0);
    for (int it = 0; it < 16; it++) {
        if (it < 15) issue((it + 1) * 32, (it + 1) & 1);
        if (it < 15) asm volatile("cp.async.wait_group 1;");
        else         asm volatile("cp.async.wait_group 0;");
        __syncthreads();
        int st = it & 1;
#pragma unroll
        for (int kk = 0; kk < 32; kk += 8) {
            unsigned a[2][4];
#pragma unroll
            for (int i = 0; i < 2; i++) {
                int r0 = wm0 + i * 16 + g;
                a[i][0] = f2tf32(sA[st][r0][kk + tg]);
                a[i][1] = f2tf32(sA[st][r0 + 8][kk + tg]);
                a[i][2] = f2tf32(sA[st][r0][kk + tg + 4]);
                a[i][3] = f2tf32(sA[st][r0 + 8][kk + tg + 4]);
            }
#pragma unroll
            for (int j = 0; j < 2; j++) {
                int nr = wn0 + j * 8 + g;
                unsigned bfr[2] = { f2tf32(sB[st][nr][kk + tg]),
                                    f2tf32(sB[st][nr][kk + tg + 4]) };
                mma16n8k8(acc[0][j], a[0], bfr);
                mma16n8k8(acc[1][j], a[1], bfr);
            }
        }
        __syncthreads();
    }

#pragma unroll
    for (int i = 0; i < 2; i++) {
#pragma unroll
        for (int up = 0; up < 2; up++) {
            int grow = row0 + wm0 + i * 16 + g + up * 8;
            if (grow < NROWS) {
#pragma unroll
                for (int j = 0; j < 2; j++) {
                    int cl = wn0 + j * 8 + 2 * tg;
                    out[grow * HH + obase + cl]     = acc[i][j][up * 2 + 0] + bsumSh[cl];
                    out[grow * HH + obase + cl + 1] = acc[i][j][up * 2 + 1] + bsumSh[cl + 1];
                }
            }
        }
    }
}

// ---------------------------------------------------------------------------
extern "C" void kernel_launch(void* const* d_in, const int* in_sizes, int n_in,
                              void* d_out, int out_size)
{
    const float* query       = (const float*)d_in[0];
    const float* key         = (const float*)d_in[1];
    const float* value       = (const float*)d_in[2];
    const void*  graph       = d_in[3];
    const float* edge_key    = (const float*)d_in[4];
    const float* edge_value  = (const float*)d_in[5];
    const float* edge_query  = (const float*)d_in[6];
    const float* Wq = (const float*)d_in[7];
    const float* bq = (const float*)d_in[8];
    const float* Wk = (const float*)d_in[9];
    const float* bk = (const float*)d_in[10];
    const float* Wv = (const float*)d_in[11];
    const float* bv = (const float*)d_in[12];
    const float* Wo = (const float*)d_in[13];
    const float* bo = (const float*)d_in[14];
    float* out = (float*)d_out;

    prep_gemm<<<dim3(144, 3), 256>>>(query, key, value, Wq, bq, Wk, bk, Wv, bv);
    attn_fused<<<558, 256>>>(graph, edge_key, edge_value, edge_query);
    out_gemm<<<136, 256>>>(Wo, bo, out);
}

// round 14
// speedup vs baseline: 1.2960x; 1.0297x over previous
#include <cuda_runtime.h>
#include <cuda_bf16.h>

#define SB 2
#define SS 513
#define HH 512
#define NHE 8
#define DD 64
#define NROWS (SB*SS)   // 1026

// Scratch (device globals — no allocation allowed)
__device__ float g_Q[SB*SS*HH];
__device__ float g_K[SB*SS*HH];
__device__ float g_V[SB*SS*HH];
__device__ float g_X[SB*SS*HH];

// ---------------------------------------------------------------------------
// helpers
// ---------------------------------------------------------------------------
__device__ __forceinline__ unsigned f2tf32(float f) {
    unsigned u; asm("cvt.rna.tf32.f32 %0, %1;" : "=r"(u) : "f"(f)); return u;
}
__device__ __forceinline__ void mma16n8k8(float* c, const unsigned* a, const unsigned* b) {
    asm volatile("mma.sync.aligned.m16n8k8.row.col.f32.tf32.tf32.f32 "
        "{%0,%1,%2,%3}, {%4,%5,%6,%7}, {%8,%9}, {%0,%1,%2,%3};"
        : "+f"(c[0]), "+f"(c[1]), "+f"(c[2]), "+f"(c[3])
        : "r"(a[0]), "r"(a[1]), "r"(a[2]), "r"(a[3]), "r"(b[0]), "r"(b[1]));
}
__device__ __forceinline__ void cp16(unsigned dst, const void* src, int sz) {
    asm volatile("cp.async.cg.shared.global [%0], [%1], 16, %2;"
                 :: "r"(dst), "l"(src), "r"(sz));
}
__device__ __forceinline__ void cp_commit() {
    asm volatile("cp.async.commit_group;");
}

// ---------------------------------------------------------------------------
// Kernel 1: grouped prep GEMM, tf32 MMA, cp.async double-buffered.
// Block tile 64(M) x 64(N), K-tile 32, 128 threads (4 warps, 32x32 warp tile:
// 256 smem-bytes/MMA vs 384 before -> lower LDS pressure + fewer issue slots).
// grid.x = 18*8 = 144, grid.y = 3 (q/k/v)
// ---------------------------------------------------------------------------
__global__ __launch_bounds__(128) void prep_gemm(
    const float* __restrict__ xq, const float* __restrict__ xk, const float* __restrict__ xv,
    const float* __restrict__ Wq, const float* __restrict__ bq,
    const float* __restrict__ Wk, const float* __restrict__ bk,
    const float* __restrict__ Wv, const float* __restrict__ bv)
{
    int z = blockIdx.y;
    const float* X = (z == 0) ? xq : (z == 1) ? xk : xv;
    const float* W = (z == 0) ? Wq : (z == 1) ? Wk : Wv;
    const float* bias = (z == 0) ? bq : (z == 1) ? bk : bv;
    float* Y = (z == 0) ? g_Q : (z == 1) ? g_K : g_V;

    int outTile = blockIdx.x & 7;        // 0..7 (64 cols each)
    int tt = blockIdx.x >> 3;            // 0..17
    int b = tt / 9;
    int w9 = tt % 9;
    int f, lt;
    if (w9 < 3) { f = w9; lt = 0; }
    else { f = 3 + (w9 - 3) / 3; lt = (w9 - 3) % 3; }
    int Nf = (f < 3) ? 57 : 171;
    int mbase = lt * 64;

    __shared__ float sA[2][64][36];
    __shared__ float sB[2][64][36];
    __shared__ int rowAddr[64];
    __shared__ float bsumSh[64];

    int tid = threadIdx.x;
    int obase = outTile * 64;

    if (tid < 64) {
        int i = mbase + tid;
        if (i < Nf) {
            int t;
            if (f < 3) t = 9 * i + f;
            else       t = 9 * (i / 3) + ((f == 3) ? 3 : 4) + 2 * (i % 3);
            rowAddr[tid] = (b * SS + t) * HH;
        } else rowAddr[tid] = -1;
    }
    if (tid >= 64) {
        int c = tid - 64;
        float s = 0.f;
#pragma unroll
        for (int ff = 0; ff < 5; ff++) s += bias[ff * HH + obase + c];
        bsumSh[c] = s;
    }
    __syncthreads();

    const float* Wf = W + f * HH * HH + obase * HH;
    unsigned aBase = (unsigned)__cvta_generic_to_shared(sA);
    unsigned bBase = (unsigned)__cvta_generic_to_shared(sB);

    int lane = tid & 31, warp = tid >> 5;
    int g = lane >> 2, tg = lane & 3;
    int wm0 = (warp & 1) * 32;
    int wn0 = (warp >> 1) * 32;

    float acc[2][4][4] = {};

    // tile issue: A 512 chunks (4/thread), B 512 chunks (4/thread), 16B each
    auto issue = [&](int k0, int stage) {
#pragma unroll
        for (int u = 0; u < 4; u++) {
            int s = tid + u * 128;
            int row = s >> 3, k4 = (s & 7) * 4;
            int ra = rowAddr[row];
            const float* src = (ra >= 0) ? &X[ra + k0 + k4] : X;
            cp16(aBase + ((stage * 64 + row) * 36 + k4) * 4, src, (ra >= 0) ? 16 : 0);
        }
#pragma unroll
        for (int u = 0; u < 4; u++) {
            int s = tid + u * 128;
            int row = s >> 3, k4 = (s & 7) * 4;
            cp16(bBase + ((stage * 64 + row) * 36 + k4) * 4, &Wf[row * HH + k0 + k4], 16);
        }
        cp_commit();
    };

    issue(0, 0);
    for (int it = 0; it < 16; it++) {
        if (it < 15) issue((it + 1) * 32, (it + 1) & 1);
        if (it < 15) asm volatile("cp.async.wait_group 1;");
        else         asm volatile("cp.async.wait_group 0;");
        __syncthreads();
        int st = it & 1;
#pragma unroll
        for (int kk = 0; kk < 32; kk += 8) {
            unsigned a[2][4];
#pragma unroll
            for (int i = 0; i < 2; i++) {
                int r0 = wm0 + i * 16 + g;
                a[i][0] = f2tf32(sA[st][r0][kk + tg]);
                a[i][1] = f2tf32(sA[st][r0 + 8][kk + tg]);
                a[i][2] = f2tf32(sA[st][r0][kk + tg + 4]);
                a[i][3] = f2tf32(sA[st][r0 + 8][kk + tg + 4]);
            }
#pragma unroll
            for (int j = 0; j < 4; j++) {
                int nr = wn0 + j * 8 + g;
                unsigned bfr[2] = { f2tf32(sB[st][nr][kk + tg]),
                                    f2tf32(sB[st][nr][kk + tg + 4]) };
                mma16n8k8(acc[0][j], a[0], bfr);
                mma16n8k8(acc[1][j], a[1], bfr);
            }
        }
        __syncthreads();
    }

#pragma unroll
    for (int i = 0; i < 2; i++) {
#pragma unroll
        for (int up = 0; up < 2; up++) {
            int mloc = wm0 + i * 16 + g + up * 8;
            int ra = rowAddr[mloc];
            if (ra >= 0) {
#pragma unroll
                for (int j = 0; j < 4; j++) {
                    int cl = wn0 + j * 8 + 2 * tg;
                    Y[ra + obase + cl]     = acc[i][j][up * 2 + 0] + bsumSh[cl];
                    Y[ra + obase + cl + 1] = acc[i][j][up * 2 + 1] + bsumSh[cl + 1];
                }
            }
        }
    }
}

// ---------------------------------------------------------------------------
// Kernel 2: fused attention (register-direct pair path). Unchanged from R13.
// ---------------------------------------------------------------------------
__device__ __forceinline__ bool graph_ok(const void* graw, bool is4, size_t idx) {
    return is4 ? (((const unsigned int*)graw)[idx] != 0u)
               : (((const unsigned char*)graw)[idx] != 0);
}

__global__ __launch_bounds__(256) void attn_fused(
    const void* __restrict__ graw,
    const float* __restrict__ ek, const float* __restrict__ ev,
    const float* __restrict__ eq)
{
    __shared__ float scratch[8 * 576];
    __shared__ float sEq[2][5][64], sEk[2][5][64], sEv[2][5][64];
    __shared__ float evs2[64];
    __shared__ int allowSm[2][5];
    __shared__ int sFlag;
    __shared__ float qrow[64];
    __shared__ float sc[516];
    __shared__ float redD[8];
    __shared__ float outred[4][64];

    int tid = threadIdx.x, lane = tid & 31, warp = tid >> 5;

    if (tid == 0) sFlag = 0;
    __syncthreads();
    {
        unsigned int w = ((const unsigned int*)graw)[tid];
        if (!(w == 0u || w == 1u || w == 0x3F800000u)) atomicOr(&sFlag, 1);
    }
    __syncthreads();
    bool is4 = (sFlag == 0);

    if (blockIdx.x >= 510) {
        int id = blockIdx.x - 510;
        int b = id / 24;
        int rem = id % 24;
        int q = rem / 8;
        int h = rem % 8;

        if (tid < 64) qrow[tid] = g_Q[((b * SS + q) * NHE + h) * DD + tid];
        __syncthreads();

        for (int k = warp; k < SS; k += 8) {
            bool ok = graph_ok(graw, is4, (size_t)(b * SS + q) * SS + k);
            const float* Kp  = &g_K[((b * SS + k) * NHE + h) * DD];
            const float* ekp = &ek[((size_t)(b * SS + q) * SS + k) * DD];
            const float* eqp = &eq[((size_t)(b * SS + k) * SS + q) * DD];
            float partial = 0.f;
#pragma unroll
            for (int r = 0; r < 2; r++) {
                int d = lane + 32 * r;
                partial += (qrow[d] + eqp[d]) * (Kp[d] + ekp[d]);
            }
#pragma unroll
            for (int o = 16; o; o >>= 1)
                partial += __shfl_xor_sync(0xFFFFFFFFu, partial, o);
            if (lane == 0) sc[k] = ok ? partial * 0.125f : -1e30f;
        }
        __syncthreads();

        float m = -1e30f;
        for (int k = tid; k < SS; k += 256) m = fmaxf(m, sc[k]);
#pragma unroll
        for (int o = 16; o; o >>= 1) m = fmaxf(m, __shfl_xor_sync(0xFFFFFFFFu, m, o));
        if (lane == 0) redD[warp] = m;
        __syncthreads();
        m = redD[0];
#pragma unroll
        for (int i = 1; i < 8; i++) m = fmaxf(m, redD[i]);
        bool uniform = (m <= -1e29f);
        __syncthreads();

        float Z = 0.f;
        for (int k = tid; k < SS; k += 256) {
            float e = uniform ? 1.0f : ((sc[k] > -1e29f) ? __expf(sc[k] - m) : 0.f);
            sc[k] = e;
            Z += e;
        }
#pragma unroll
        for (int o = 16; o; o >>= 1) Z += __shfl_xor_sync(0xFFFFFFFFu, Z, o);
        if (lane == 0) redD[warp] = Z;
        __syncthreads();
        Z = 0.f;
#pragma unroll
        for (int i = 0; i < 8; i++) Z += redD[i];
        float invZ = 1.f / Z;
        __syncthreads();

        int d = tid & 63, p = tid >> 6;
        float acc = 0.f;
        for (int k = p; k < SS; k += 4)
            acc += sc[k] * (g_V[((b * SS + k) * NHE + h) * DD + d] +
                            ev[((size_t)(b * SS + q) * SS + k) * DD + d]);
        outred[p][d] = acc;
        __syncthreads();
        if (p == 0)
            g_X[((b * SS + q) * NHE + h) * DD + d] =
                (outred[0][d] + outred[1][d] + outred[2][d] + outred[3][d]) * invZ;
        return;
    }

    int pid = blockIdx.x;
    int b = pid / 255;
    int pr = pid % 255;
    int q0 = 3 + 2 * pr;
    int cand[5];
    cand[0] = 0; cand[1] = 1; cand[2] = 2; cand[3] = q0; cand[4] = q0 + 1;

    if (tid < 10) {
        int qq = tid / 5, j = tid % 5;
        allowSm[qq][j] =
            graph_ok(graw, is4, (size_t)(b * SS + q0 + qq) * SS + cand[j]) ? 1 : 0;
    }

    int h = warp;
    float qr[2][2], kr[5][2], vr[5][2];
#pragma unroll
    for (int qq = 0; qq < 2; qq++) {
        const float* Qp = &g_Q[(b * SS + q0 + qq) * HH + h * 64];
#pragma unroll
        for (int r = 0; r < 2; r++) qr[qq][r] = Qp[lane + 32 * r];
    }
#pragma unroll
    for (int j = 0; j < 5; j++) {
        const float* Kp = &g_K[(b * SS + cand[j]) * HH + h * 64];
        const float* Vp = &g_V[(b * SS + cand[j]) * HH + h * 64];
#pragma unroll
        for (int r = 0; r < 2; r++) {
            kr[j][r] = Kp[lane + 32 * r];
            vr[j][r] = Vp[lane + 32 * r];
        }
    }

    for (int i = tid; i < 640; i += 256) {
        int qq = i / 320, j = (i / 64) % 5, d = i & 63;
        int q = q0 + qq, c = cand[j];
        size_t eidx = ((size_t)(b * SS + q) * SS + c) * DD + d;
        sEk[qq][j][d] = ek[eidx];
        sEv[qq][j][d] = ev[eidx];
        sEq[qq][j][d] = eq[((size_t)(b * SS + c) * SS + q) * DD + d];
    }
    __syncthreads();

    int nA[2];
#pragma unroll
    for (int qq = 0; qq < 2; qq++)
        nA[qq] = allowSm[qq][0] + allowSm[qq][1] + allowSm[qq][2] +
                 allowSm[qq][3] + allowSm[qq][4];

#pragma unroll
    for (int qq = 0; qq < 2; qq++) {
        if (nA[qq] == 0) continue;
        float s[5];
#pragma unroll
        for (int j = 0; j < 5; j++) {
            float partial = 0.f;
#pragma unroll
            for (int r = 0; r < 2; r++) {
                int d = lane + r * 32;
                partial += (qr[qq][r] + sEq[qq][j][d]) * (kr[j][r] + sEk[qq][j][d]);
            }
#pragma unroll
            for (int o = 16; o; o >>= 1)
                partial += __shfl_xor_sync(0xFFFFFFFFu, partial, o);
            s[j] = partial;
        }
        const float scale = 0.125f;
        float m = -1e30f;
#pragma unroll
        for (int j = 0; j < 5; j++)
            if (allowSm[qq][j]) m = fmaxf(m, s[j] * scale);
        float w[5]; float Z = 0.f;
#pragma unroll
        for (int j = 0; j < 5; j++) {
            w[j] = allowSm[qq][j] ? __expf(s[j] * scale - m) : 0.f;
            Z += w[j];
        }
        float invZ = 1.f / Z;
#pragma unroll
        for (int r = 0; r < 2; r++) {
            int d = lane + r * 32;
            float acc = 0.f;
#pragma unroll
            for (int j = 0; j < 5; j++)
                acc += w[j] * invZ * (vr[j][r] + sEv[qq][j][d]);
            g_X[(b * SS + q0 + qq) * HH + h * 64 + d] = acc;
        }
    }

    if (nA[0] > 0 && nA[1] > 0) return;
    __syncthreads();

#pragma unroll
    for (int qq = 0; qq < 2; qq++) {
        if (nA[qq] > 0) continue;
        int q = q0 + qq;
        float4 va[4] = { make_float4(0.f,0.f,0.f,0.f), make_float4(0.f,0.f,0.f,0.f),
                         make_float4(0.f,0.f,0.f,0.f), make_float4(0.f,0.f,0.f,0.f) };
        float ea0 = 0.f, ea1 = 0.f;
        for (int k = warp; k < SS; k += 8) {
            const float4* vrow = (const float4*)(g_V + (b * SS + k) * HH);
#pragma unroll
            for (int c = 0; c < 4; c++) {
                float4 v = vrow[lane + 32 * c];
                va[c].x += v.x; va[c].y += v.y; va[c].z += v.z; va[c].w += v.w;
            }
            const float* er = ev + ((size_t)(b * SS + q) * SS + k) * DD;
            ea0 += er[lane];
            ea1 += er[lane + 32];
        }
        float* red = scratch;
#pragma unroll
        for (int c = 0; c < 4; c++)
            ((float4*)(red + warp * 576))[lane + 32 * c] = va[c];
        red[warp * 576 + 512 + lane] = ea0;
        red[warp * 576 + 544 + lane] = ea1;
        __syncthreads();
        if (tid < 64) {
            float s = 0.f;
#pragma unroll
            for (int w8 = 0; w8 < 8; w8++) s += red[w8 * 576 + 512 + tid];
            evs2[tid] = s;
        }
        __syncthreads();
#pragma unroll
        for (int e = 0; e < 2; e++) {
            int idx = tid + 256 * e;
            float s = 0.f;
#pragma unroll
            for (int w8 = 0; w8 < 8; w8++) s += red[w8 * 576 + idx];
            g_X[(b * SS + q) * HH + idx] = (s + evs2[idx & 63]) * (1.0f / 513.0f);
        }
        __syncthreads();
    }
}

// ---------------------------------------------------------------------------
// Kernel 3: output projection, tf32 MMA, cp.async double-buffered.
// Block tile 64(M) x 64(N), K-tile 32. grid.x = 136  (R11 measured best)
// ---------------------------------------------------------------------------
__global__ __launch_bounds__(256) void out_gemm(
    const float* __restrict__ Wo, const float* __restrict__ bo,
    float* __restrict__ out)
{
    int outTile = blockIdx.x & 7;
    int mt = blockIdx.x >> 3;       // 0..16
    int row0 = mt * 64;
    int obase = outTile * 64;

    __shared__ float sA[2][64][36];
    __shared__ float sB[2][64][36];
    __shared__ float bsumSh[64];

    int tid = threadIdx.x;
    int lane = tid & 31, warp = tid >> 5;
    int g = lane >> 2, tg = lane & 3;
    int wm0 = (warp & 1) * 32;
    int wn0 = (warp >> 1) * 16;

    const float* Wf = Wo + obase * HH;
    unsigned aBase = (unsigned)__cvta_generic_to_shared(sA);
    unsigned bBase = (unsigned)__cvta_generic_to_shared(sB);

    if (tid < 64) bsumSh[tid] = bo[obase + tid];
    __syncthreads();

    float acc[2][2][4] = {};

    auto issue = [&](int k0, int stage) {
#pragma unroll
        for (int u = 0; u < 2; u++) {
            int s = tid + u * 256;
            int row = s >> 3, k4 = (s & 7) * 4;
            int grow = row0 + row;
            const float* src = (grow < NROWS) ? &g_X[grow * HH + k0 + k4] : g_X;
            cp16(aBase + ((stage * 64 + row) * 36 + k4) * 4, src, (grow < NROWS) ? 16 : 0);
        }
#pragma unroll
        for (int u = 0; u < 2; u++) {
            int s = tid + u * 256;
            int row = s >> 3, k4 = (s & 7) * 4;
            cp16(bBase + ((stage * 64 + row) * 36 + k4) * 4, &Wf[row * HH + k0 + k4], 16);
        }
        cp_commit();
    };

    issue(0, 0);
    for (int it = 0; it < 16; it++) {
        if (it < 15) issue((it + 1) * 32, (it + 1) & 1);
        if (it < 15) asm volatile("cp.async.wait_group 1;");
        else         asm volatile("cp.async.wait_group 0;");
        __syncthreads();
        int st = it & 1;
#pragma unroll
        for (int kk = 0; kk < 32; kk += 8) {
            unsigned a[2][4];
#pragma unroll
            for (int i = 0; i < 2; i++) {
                int r0 = wm0 + i * 16 + g;
                a[i][0] = f2tf32(sA[st][r0][kk + tg]);
                a[i][1] = f2tf32(sA[st][r0 + 8][kk + tg]);
                a[i][2] = f2tf32(sA[st][r0][kk + tg + 4]);
                a[i][3] = f2tf32(sA[st][r0 + 8][kk + tg + 4]);
            }
#pragma unroll
            for (int j = 0; j < 2; j++) {
                int nr = wn0 + j * 8 + g;
                unsigned bfr[2] = { f2tf32(sB[st][nr][kk + tg]),
                                    f2tf32(sB[st][nr][kk + tg + 4]) };
                mma16n8k8(acc[0][j], a[0], bfr);
                mma16n8k8(acc[1][j], a[1], bfr);
            }
        }
        __syncthreads();
    }

#pragma unroll
    for (int i = 0; i < 2; i++) {
#pragma unroll
        for (int up = 0; up < 2; up++) {
            int grow = row0 + wm0 + i * 16 + g + up * 8;
            if (grow < NROWS) {
#pragma unroll
                for (int j = 0; j < 2; j++) {
                    int cl = wn0 + j * 8 + 2 * tg;
                    out[grow * HH + obase + cl]     = acc[i][j][up * 2 + 0] + bsumSh[cl];
                    out[grow * HH + obase + cl + 1] = acc[i][j][up * 2 + 1] + bsumSh[cl + 1];
                }
            }
        }
    }
}

// ---------------------------------------------------------------------------
extern "C" void kernel_launch(void* const* d_in, const int* in_sizes, int n_in,
                              void* d_out, int out_size)
{
    const float* query       = (const float*)d_in[0];
    const float* key         = (const float*)d_in[1];
    const float* value       = (const float*)d_in[2];
    const void*  graph       = d_in[3];
    const float* edge_key    = (const float*)d_in[4];
    const float* edge_value  = (const float*)d_in[5];
    const float* edge_query  = (const float*)d_in[6];
    const float* Wq = (const float*)d_in[7];
    const float* bq = (const float*)d_in[8];
    const float* Wk = (const float*)d_in[9];
    const float* bk = (const float*)d_in[10];
    const float* Wv = (const float*)d_in[11];
    const float* bv = (const float*)d_in[12];
    const float* Wo = (const float*)d_in[13];
    const float* bo = (const float*)d_in[14];
    float* out = (float*)d_out;

    prep_gemm<<<dim3(144, 3), 128>>>(query, key, value, Wq, bq, Wk, bk, Wv, bv);
    attn_fused<<<558, 256>>>(graph, edge_key, edge_value, edge_query);
    out_gemm<<<136, 256>>>(Wo, bo, out);
}